// round 15
// baseline (speedup 1.0000x reference)
#include <cuda_runtime.h>
#include <cuda_bf16.h>
#include <cstddef>

// Problem constants (fixed shapes per reference)
constexpr int B_ = 16;
constexpr int C_ = 256;
constexpr int L_ = 8192;
constexpr int D_ = 512;   // d_inner
constexpr int A_ = 64;    // att_dim

// Scratch: u[d] = sum_a w_out[d,a]*wv[a]; coef = <wq,wk>/sqrt(att_dim)
__device__ float g_u[D_];
__device__ float g_coef;

// Fast prep: 32 blocks x 256 threads; global thread i handles float4 chunk i
// of w_out (8192 chunks). Coalesced, 16-lane shuffle reduce, STG per row.
__global__ void prep_kernel(const float* __restrict__ wq,
                            const float* __restrict__ wk,
                            const float* __restrict__ wv,
                            const float* __restrict__ w_out) {
    const int t   = threadIdx.x;
    const int idx = blockIdx.x * 256 + t;      // 0..8191 float4 chunks
    const int q   = idx & 15;
    const int row = idx >> 4;

    const float4 vv = reinterpret_cast<const float4*>(wv)[q];
    const float4 r  = reinterpret_cast<const float4*>(w_out)[idx];
    float acc = r.x * vv.x + r.y * vv.y + r.z * vv.z + r.w * vv.w;
    acc += __shfl_xor_sync(0xffffffffu, acc, 8);
    acc += __shfl_xor_sync(0xffffffffu, acc, 4);
    acc += __shfl_xor_sync(0xffffffffu, acc, 2);
    acc += __shfl_xor_sync(0xffffffffu, acc, 1);
    if (q == 0) g_u[row] = acc;

    if (blockIdx.x == 0 && t < 32) {
        float p = wq[t] * wk[t] + wq[t + 32] * wk[t + 32];
#pragma unroll
        for (int m = 16; m >= 1; m >>= 1)
            p += __shfl_xor_sync(0xffffffffu, p, m);
        if (t == 0) g_coef = p * 0.125f;  // 1/sqrt(64)
    }
}

// Main kernel: SMALL-CTA variant of the proven R8 structure.
// One block = (one b, 8 consecutive l). 128 threads = 16 c-groups x 8 l.
// Each thread keeps 16 h values in registers -> h_v read exactly once.
// Halved convoy unit (4 warps/barrier) + ~13 CTAs/SM for deeper interleave.
__global__ void __launch_bounds__(128, 12)
pool_outer_kernel(const float* __restrict__ h_v, float* __restrict__ out) {
    __shared__ float s_u[D_];
    __shared__ float s_red[128];
    __shared__ float s_red2[128];
    __shared__ float s_sval[8];
    __shared__ __align__(16) float s_pooled[8];

    const int tid = threadIdx.x;
    const int ll  = tid & 7;    // l within tile
    const int cg  = tid >> 3;   // c-group 0..15 (16 c each)

    const int bidx   = blockIdx.x;          // 16 * 1024 = 16384 blocks
    const int b      = bidx >> 10;
    const int l_base = (bidx & 1023) << 3;

    const float coef = g_coef;

    // stage u into smem (4 per thread, L2-hot)
    s_u[tid]       = g_u[tid];
    s_u[tid + 128] = g_u[tid + 128];
    s_u[tid + 256] = g_u[tid + 256];
    s_u[tid + 384] = g_u[tid + 384];

    // ---- single read of h_v: 16 values per thread (imm-offset LDGs) ----
    const float* p = h_v + ((size_t)b * C_ + (size_t)cg * 16) * L_ + l_base + ll;
    float h[16];
#pragma unroll
    for (int i = 0; i < 16; i++) h[i] = __ldcs(p + (size_t)i * L_);

    // ---- mean over C ----
    float sum = 0.f;
#pragma unroll
    for (int i = 0; i < 16; i++) sum += h[i];
    s_red[tid] = sum;
    __syncthreads();
    if (tid < 8) {
        float t = 0.f;
#pragma unroll
        for (int j = 0; j < 16; j++) t += s_red[tid + 8 * j];
        s_sval[tid] = t * ((1.0f / 256.0f) * coef);  // fold mean scale + qk/sqrt(A)
    }
    __syncthreads();

    const float coef2 = s_sval[ll];  // per-l logit scale

    // ---- softmax-weighted sum (max-free: |logit| bounded ~1.2) ----
    float se = 0.f, seh = 0.f;
#pragma unroll
    for (int i = 0; i < 16; i++) {
        float e = __expf(h[i] * coef2);
        se  += e;
        seh += e * h[i];
    }
    s_red[tid]  = se;
    s_red2[tid] = seh;
    __syncthreads();
    if (tid < 8) {
        float te = 0.f, teh = 0.f;
#pragma unroll
        for (int j = 0; j < 16; j++) {
            te  += s_red[tid + 8 * j];
            teh += s_red2[tid + 8 * j];
        }
        s_pooled[tid] = teh / te;
    }
    __syncthreads();

    // ---- epilogue: out[b,d,l] = pooled[l] * u[d], float4 streaming stores.
    // 512 d-rows x 2 float4 = 1024 vec stores per block; 8 per thread.
    const int lq = tid & 1;
    const int d0 = tid >> 1;
    const float4 pv = reinterpret_cast<const float4*>(s_pooled)[lq];
    float4* out4 = reinterpret_cast<float4*>(out + (size_t)b * D_ * L_ + l_base) + lq;
#pragma unroll
    for (int k = 0; k < 8; k++) {
        int d = d0 + 64 * k;
        float ud = s_u[d];
        __stcs(&out4[(size_t)d * (L_ / 4)],
               make_float4(pv.x * ud, pv.y * ud, pv.z * ud, pv.w * ud));
    }
}

extern "C" void kernel_launch(void* const* d_in, const int* in_sizes, int n_in,
                              void* d_out, int out_size) {
    const float* h_v   = (const float*)d_in[0];  // [B, C, L]
    const float* wq    = (const float*)d_in[1];  // [64]
    const float* wk    = (const float*)d_in[2];  // [64]
    const float* wv    = (const float*)d_in[3];  // [64]
    const float* w_out = (const float*)d_in[4];  // [512, 64]
    float* out = (float*)d_out;                  // [B, 512, L]

    prep_kernel<<<(D_ * A_ / 4) / 256, 256>>>(wq, wk, wv, w_out);
    pool_outer_kernel<<<B_ * (L_ / 8), 128>>>(h_v, out);
}

// round 17
// speedup vs baseline: 1.1872x; 1.1872x over previous
#include <cuda_runtime.h>
#include <cuda_bf16.h>
#include <cstddef>

// Problem constants (fixed shapes per reference)
constexpr int B_ = 16;
constexpr int C_ = 256;
constexpr int L_ = 8192;
constexpr int D_ = 512;   // d_inner
constexpr int A_ = 64;    // att_dim

// Scratch: u[d] = sum_a w_out[d,a]*wv[a]; coef = <wq,wk>/sqrt(att_dim)
__device__ float g_u[D_];
__device__ float g_coef;

// Fast prep: 32 blocks x 256 threads; global thread i handles float4 chunk i
// of w_out (8192 chunks). Coalesced, 16-lane shuffle reduce, STG per row.
__global__ void prep_kernel(const float* __restrict__ wq,
                            const float* __restrict__ wk,
                            const float* __restrict__ wv,
                            const float* __restrict__ w_out) {
    const int t   = threadIdx.x;
    const int idx = blockIdx.x * 256 + t;      // 0..8191 float4 chunks
    const int q   = idx & 15;
    const int row = idx >> 4;

    const float4 vv = reinterpret_cast<const float4*>(wv)[q];
    const float4 r  = reinterpret_cast<const float4*>(w_out)[idx];
    float acc = r.x * vv.x + r.y * vv.y + r.z * vv.z + r.w * vv.w;
    acc += __shfl_xor_sync(0xffffffffu, acc, 8);
    acc += __shfl_xor_sync(0xffffffffu, acc, 4);
    acc += __shfl_xor_sync(0xffffffffu, acc, 2);
    acc += __shfl_xor_sync(0xffffffffu, acc, 1);
    if (q == 0) g_u[row] = acc;

    if (blockIdx.x == 0 && t < 32) {
        float p = wq[t] * wk[t] + wq[t + 32] * wk[t + 32];
#pragma unroll
        for (int m = 16; m >= 1; m >>= 1)
            p += __shfl_xor_sync(0xffffffffu, p, m);
        if (t == 0) g_coef = p * 0.125f;  // 1/sqrt(64)
    }
}

// Main kernel: R8 structure (60.0us, measured x4), launched with PDL so it
// overlaps the prep kernel. Each block issues its h_v LDG burst, THEN waits
// on the upstream (prep) completion via cudaGridDependencySynchronize(), then
// stages coef/u — the dependency hides under launch ramp + DRAM load latency.
__global__ void __launch_bounds__(256, 6)
pool_outer_kernel(const float* __restrict__ h_v, float* __restrict__ out) {
    __shared__ float s_u[D_];
    __shared__ float s_red[256];
    __shared__ float s_red2[256];
    __shared__ float s_sval[16];
    __shared__ __align__(16) float s_pooled[16];

    const int tid = threadIdx.x;
    const int ll  = tid & 15;   // l within tile
    const int cg  = tid >> 4;   // c-group 0..15 (16 c each)

    const int bidx   = blockIdx.x;          // 16 * 512 = 8192 blocks
    const int b      = bidx >> 9;
    const int l_base = (bidx & 511) << 4;

    // ---- single read of h_v: 16 values per thread (imm-offset LDG burst) ----
    const float* p = h_v + ((size_t)b * C_ + (size_t)cg * 16) * L_ + l_base + ll;
    float h[16];
#pragma unroll
    for (int i = 0; i < 16; i++) h[i] = __ldcs(p + (size_t)i * L_);

    // ---- wait for prep (overlapped with the in-flight loads above) ----
#if __CUDA_ARCH__ >= 900
    cudaGridDependencySynchronize();
#endif
    const float coef = g_coef;
    s_u[tid]       = g_u[tid];
    s_u[tid + 256] = g_u[tid + 256];

    // ---- mean over C ----
    float sum = 0.f;
#pragma unroll
    for (int i = 0; i < 16; i++) sum += h[i];
    s_red[tid] = sum;
    __syncthreads();
    if (tid < 16) {
        float t = 0.f;
#pragma unroll
        for (int j = 0; j < 16; j++) t += s_red[tid + 16 * j];
        s_sval[tid] = t * ((1.0f / 256.0f) * coef);
    }
    __syncthreads();

    const float coef2 = s_sval[ll];  // per-l logit scale

    // ---- softmax-weighted sum (max-free: |logit| bounded ~1.2) ----
    float se = 0.f, seh = 0.f;
#pragma unroll
    for (int i = 0; i < 16; i++) {
        float e = __expf(h[i] * coef2);
        se  += e;
        seh += e * h[i];
    }
    s_red[tid]  = se;
    s_red2[tid] = seh;
    __syncthreads();
    if (tid < 16) {
        float te = 0.f, teh = 0.f;
#pragma unroll
        for (int j = 0; j < 16; j++) {
            te  += s_red[tid + 16 * j];
            teh += s_red2[tid + 16 * j];
        }
        s_pooled[tid] = teh / te;
    }
    __syncthreads();   // also covers s_u visibility for the epilogue

    // ---- epilogue: out[b,d,l] = pooled[l] * u[d], float4 streaming stores ----
    const int lq = tid & 3;
    const int d0 = tid >> 2;
    const float4 pv = reinterpret_cast<const float4*>(s_pooled)[lq];
    float4* out4 = reinterpret_cast<float4*>(out + (size_t)b * D_ * L_ + l_base) + lq;
#pragma unroll
    for (int k = 0; k < 8; k++) {
        int d = d0 + 64 * k;
        float ud = s_u[d];
        __stcs(&out4[(size_t)d * (L_ / 4)],
               make_float4(pv.x * ud, pv.y * ud, pv.z * ud, pv.w * ud));
    }
}

extern "C" void kernel_launch(void* const* d_in, const int* in_sizes, int n_in,
                              void* d_out, int out_size) {
    const float* h_v   = (const float*)d_in[0];  // [B, C, L]
    const float* wq    = (const float*)d_in[1];  // [64]
    const float* wk    = (const float*)d_in[2];  // [64]
    const float* wv    = (const float*)d_in[3];  // [64]
    const float* w_out = (const float*)d_in[4];  // [512, 64]
    float* out = (float*)d_out;                  // [B, 512, L]

    // Upstream: tiny prep (u and coef).
    prep_kernel<<<(D_ * A_ / 4) / 256, 256>>>(wq, wk, wv, w_out);

    // Downstream: main kernel with programmatic dependent launch, so it
    // ramps up concurrently with prep and only gridsync's before using u.
    cudaLaunchAttribute attrs[1];
    attrs[0].id = cudaLaunchAttributeProgrammaticStreamSerialization;
    attrs[0].val.programmaticStreamSerializationAllowed = 1;

    cudaLaunchConfig_t cfg = {};
    cfg.gridDim  = dim3(B_ * (L_ / 16), 1, 1);
    cfg.blockDim = dim3(256, 1, 1);
    cfg.dynamicSmemBytes = 0;
    cfg.stream = 0;            // capture/legacy stream (same as <<<>>> above)
    cfg.attrs = attrs;
    cfg.numAttrs = 1;

    cudaLaunchKernelEx(&cfg, pool_outer_kernel, h_v, out);
}